// round 15
// baseline (speedup 1.0000x reference)
#include <cuda_runtime.h>
#include <cuda_bf16.h>
#include <cuda_fp16.h>
#include <stdint.h>
#include <stddef.h>

// ============================================================================
// WindowAttention on sm_103 (baseline ISA: mma.sync HMMA, cp.async, ldmatrix)
//   qkv = x @ [Wq|Wk|Wv] + b      (M=100352, K=1024, N=1536, Wv zero-padded)
//   attn = softmax(q k^T * 0.125 + mask[b%256]) ; att = attn @ v
//   out  = att @ Wp + bp          (M=100352, K=512,  N=1024)
// R14: register double-buffered ldmatrix fragments in the gemm mainloop —
//      prefetch ks+1 LDSMs before ks MMAs so the exposed LDSM->HMMA latency
//      (cause of R13's tensor 46%) is hidden within each warp.
// GEMMs 1-pass fp16 (measured 5.38e-4 vs 1e-3 gate); attention bf16 3-pass.
// ============================================================================

#define M_ROWS   100352
#define N_QKV    1536
#define K_QKV    1024
#define N_PROJ   1024
#define K_PROJ   512

// ---------------- scratch (device globals; no allocation allowed) -----------
__device__ __align__(16) float   g_qkv[(size_t)M_ROWS * N_QKV];
__device__ __align__(16) __half  g_x[(size_t)M_ROWS * K_QKV];
__device__ __align__(16) __half  g_att[(size_t)M_ROWS * K_PROJ];
__device__ __align__(16) __half  g_wqkv[(size_t)N_QKV * K_QKV];
__device__ __align__(16) __half  g_wp[(size_t)N_PROJ * K_PROJ];
__device__ float g_bqkv[N_QKV];

// ---------------- helpers ----------------------------------------------------
__device__ __forceinline__ uint32_t smem_u32(const void* p) {
    uint32_t a;
    asm("{ .reg .u64 t; cvta.to.shared.u64 t, %1; cvt.u32.u64 %0, t; }"
        : "=r"(a) : "l"(p));
    return a;
}

__device__ __forceinline__ void split_bf16(float x, __nv_bfloat16& h, __nv_bfloat16& l) {
    h = __float2bfloat16_rn(x);
    l = __float2bfloat16_rn(x - __bfloat162float(h));
}
__device__ __forceinline__ uint32_t pack2(__nv_bfloat16 a, __nv_bfloat16 b) {
    return ((uint32_t)__bfloat16_as_ushort(b) << 16) | (uint32_t)__bfloat16_as_ushort(a);
}
__device__ __forceinline__ uint32_t pack2h(__half a, __half b) {
    return ((uint32_t)__half_as_ushort(b) << 16) | (uint32_t)__half_as_ushort(a);
}

#define CP16(dst, src) \
    asm volatile("cp.async.cg.shared.global [%0], [%1], 16;" \
                 :: "r"(dst), "l"(src))
#define CP_COMMIT() asm volatile("cp.async.commit_group;" ::: "memory")
#define CP_WAIT0()  asm volatile("cp.async.wait_group 0;" ::: "memory")
#define CP_WAIT1()  asm volatile("cp.async.wait_group 1;" ::: "memory")

#define LDMX4(r0, r1, r2, r3, addr) \
    asm volatile("ldmatrix.sync.aligned.m8n8.x4.shared.b16 {%0,%1,%2,%3}, [%4];" \
                 : "=r"(r0), "=r"(r1), "=r"(r2), "=r"(r3) : "r"(addr))

#define MMA16816BF(d, a, b0, b1) \
    asm volatile("mma.sync.aligned.m16n8k16.row.col.f32.bf16.bf16.f32 " \
                 "{%0,%1,%2,%3}, {%4,%5,%6,%7}, {%8,%9}, {%0,%1,%2,%3};" \
                 : "+f"((d)[0]), "+f"((d)[1]), "+f"((d)[2]), "+f"((d)[3]) \
                 : "r"((a)[0]), "r"((a)[1]), "r"((a)[2]), "r"((a)[3]), \
                   "r"(b0), "r"(b1))

#define MMA16816H(d, a, b0, b1) \
    asm volatile("mma.sync.aligned.m16n8k16.row.col.f32.f16.f16.f32 " \
                 "{%0,%1,%2,%3}, {%4,%5,%6,%7}, {%8,%9}, {%0,%1,%2,%3};" \
                 : "+f"((d)[0]), "+f"((d)[1]), "+f"((d)[2]), "+f"((d)[3]) \
                 : "r"((a)[0]), "r"((a)[1]), "r"((a)[2]), "r"((a)[3]), \
                   "r"(b0), "r"(b1))

// ============================================================================
// prep: weights (transposed, fused, fp16) + bias
// ============================================================================
__global__ void prep_w_kernel(const float* __restrict__ Wq, const float* __restrict__ Wk,
                              const float* __restrict__ Wv, const float* __restrict__ bq,
                              const float* __restrict__ bk, const float* __restrict__ bv,
                              const float* __restrict__ Wp)
{
    const int T1 = N_QKV * K_QKV;
    const int T2 = N_PROJ * K_PROJ;
    const int TOT = T1 + T2 + N_QKV;
    int stride = gridDim.x * blockDim.x;
    for (int idx = blockIdx.x * blockDim.x + threadIdx.x; idx < TOT; idx += stride) {
        if (idx < T1) {
            int n = idx >> 10, k = idx & 1023;
            float w;
            if (n < 512)       w = Wq[k * 512 + n];
            else if (n < 1024) w = Wk[k * 512 + (n - 512)];
            else               w = (k < 512) ? Wv[k * 512 + (n - 1024)] : 0.f;
            g_wqkv[idx] = __float2half_rn(w);
        } else if (idx < T1 + T2) {
            int i = idx - T1;
            int n = i >> 9, k = i & 511;
            g_wp[i] = __float2half_rn(Wp[k * 1024 + n]);
        } else {
            int n = idx - T1 - T2;
            g_bqkv[n] = (n < 512) ? bq[n] : (n < 1024) ? bk[n - 512] : bv[n - 1024];
        }
    }
}

// x[M][1024] f32 -> fp16 (8 floats per task)
__global__ void prep_x_kernel(const float* __restrict__ x)
{
    const size_t TOT = (size_t)M_ROWS * K_QKV / 8;
    size_t stride = (size_t)gridDim.x * blockDim.x;
    for (size_t t = blockIdx.x * (size_t)blockDim.x + threadIdx.x; t < TOT; t += stride) {
        const float4* src = (const float4*)(x + t * 8);
        float4 f0 = src[0], f1 = src[1];
        float v[8] = {f0.x, f0.y, f0.z, f0.w, f1.x, f1.y, f1.z, f1.w};
        __half h[8];
        #pragma unroll
        for (int e = 0; e < 8; ++e) h[e] = __float2half_rn(v[e]);
        *(uint4*)(g_x + t * 8) = *(uint4*)h;
    }
}

// ============================================================================
// 1-pass fp16 GEMM: C = fp16(A) @ fp16(B)^T + bias
//   CTA tile 128x256, K-chunk 128, 8 warps (2x4 -> warp tile 64x64)
//   Register double-buffered fragments: LDSM(ks+1) issued before MMA(ks).
// ============================================================================
#define ROWB    272                 // padded row bytes (136 fp16; 128 data)
#define ARRB_A  34816               // 128*272
#define ARRB_B  69632               // 256*272
#define OFF_B   34816
#define STAGEB  104448              // ARRB_A + ARRB_B
#define GEMM_SMEM (2 * STAGEB)      // 208896

__global__ void __launch_bounds__(256, 1) gemm_kernel(
    const __half* __restrict__ A, int lda,
    const __half* __restrict__ B, int ldb,
    const float* __restrict__ bias,
    float* __restrict__ C, int ldc,
    int n_tiles, int k_chunks)
{
    extern __shared__ char smem[];
    uint32_t sbase = smem_u32(smem);
    int tid = threadIdx.x, wid = tid >> 5, lane = tid & 31;
    int nt = blockIdx.x % n_tiles, mt = blockIdx.x / n_tiles;
    int m0 = mt * 128, n0 = nt * 256;

    int warp_m = (wid >> 2) * 64;         // 0 or 64
    int warp_n = (wid & 3) * 64;          // 0,64,128,192

    uint32_t aoff = (uint32_t)((warp_m + (lane & 15)) * ROWB + (lane >> 4) * 16);
    uint32_t boff = (uint32_t)((warp_n + ((lane >> 4) << 3) + (lane & 7)) * ROWB
                               + (((lane >> 3) & 1) << 4));

    float acc[4][8][4];
    #pragma unroll
    for (int i = 0; i < 4; ++i)
        #pragma unroll
        for (int j = 0; j < 8; ++j)
            #pragma unroll
            for (int e = 0; e < 4; ++e) acc[i][j][e] = 0.f;

    auto load_chunk = [&](int c) {
        uint32_t sb = sbase + (uint32_t)(c & 1) * STAGEB;
        const __half* Ap = A + (size_t)m0 * lda + c * 128;
        const __half* Bp = B + (size_t)n0 * ldb + c * 128;
        #pragma unroll
        for (int q = 0; q < 8; ++q) {
            int t = tid + q * 256;
            int r = t >> 4, j = t & 15;
            uint32_t dst = sb + (uint32_t)(r * ROWB + j * 16);
            const void* src = Ap + (size_t)r * lda + j * 8;
            CP16(dst, src);
        }
        #pragma unroll
        for (int q = 0; q < 16; ++q) {
            int t = tid + q * 256;
            int r = (t >> 4) & 255, j = t & 15;
            uint32_t dst = sb + OFF_B + (uint32_t)(r * ROWB + j * 16);
            const void* src = Bp + (size_t)r * ldb + j * 8;
            CP16(dst, src);
        }
    };

    load_chunk(0);
    CP_COMMIT();

    uint32_t bfr[2][16], afr[2][16];

    for (int c = 0; c < k_chunks; ++c) {
        if (c + 1 < k_chunks) { load_chunk(c + 1); CP_COMMIT(); CP_WAIT1(); }
        else                  { CP_WAIT0(); }
        __syncthreads();

        uint32_t sb = sbase + (uint32_t)(c & 1) * STAGEB;
        uint32_t sA = sb + aoff;
        uint32_t sB = sb + OFF_B + boff;

        // prologue: fragments for ks=0
        #pragma unroll
        for (int nb = 0; nb < 4; ++nb)
            LDMX4(bfr[0][4*nb], bfr[0][4*nb+1], bfr[0][4*nb+2], bfr[0][4*nb+3],
                  sB + (uint32_t)(nb * 16 * ROWB));
        #pragma unroll
        for (int mi = 0; mi < 4; ++mi)
            LDMX4(afr[0][4*mi], afr[0][4*mi+1], afr[0][4*mi+2], afr[0][4*mi+3],
                  sA + (uint32_t)(mi * 16 * ROWB));

        #pragma unroll
        for (int ks = 0; ks < 8; ++ks) {
            const int cur = ks & 1, nxt = cur ^ 1;
            if (ks < 7) {
                uint32_t kb = (uint32_t)((ks + 1) * 32);
                #pragma unroll
                for (int nb = 0; nb < 4; ++nb)
                    LDMX4(bfr[nxt][4*nb], bfr[nxt][4*nb+1],
                          bfr[nxt][4*nb+2], bfr[nxt][4*nb+3],
                          sB + kb + (uint32_t)(nb * 16 * ROWB));
                #pragma unroll
                for (int mi = 0; mi < 4; ++mi)
                    LDMX4(afr[nxt][4*mi], afr[nxt][4*mi+1],
                          afr[nxt][4*mi+2], afr[nxt][4*mi+3],
                          sA + kb + (uint32_t)(mi * 16 * ROWB));
            }
            #pragma unroll
            for (int mi = 0; mi < 4; ++mi) {
                #pragma unroll
                for (int ni = 0; ni < 8; ++ni) {
                    MMA16816H(acc[mi][ni], &afr[cur][4*mi],
                              bfr[cur][2*ni], bfr[cur][2*ni+1]);
                }
            }
        }
        __syncthreads();
    }

    #pragma unroll
    for (int mi = 0; mi < 4; ++mi) {
        int m = m0 + warp_m + mi * 16 + (lane >> 2);
        #pragma unroll
        for (int ni = 0; ni < 8; ++ni) {
            int n = n0 + warp_n + ni * 8 + (lane & 3) * 2;
            float b0 = bias[n], b1 = bias[n + 1];
            float2* p0 = (float2*)(C + (size_t)m * ldc + n);
            float2* p1 = (float2*)(C + (size_t)(m + 8) * ldc + n);
            *p0 = make_float2(acc[mi][ni][0] + b0, acc[mi][ni][1] + b1);
            *p1 = make_float2(acc[mi][ni][2] + b0, acc[mi][ni][3] + b1);
        }
    }
}

// ============================================================================
// HMMA attention (bf16 3-pass internally): CTA per (window b, head h), 4 warps.
// Output stored as plain fp16 for the 1-pass GEMM2.
// ============================================================================
#define AT_QH 0
#define AT_QL 9216
#define AT_KH 18432
#define AT_KL 27648
#define AT_VH 36864
#define AT_VL 46080
#define ATTN_SMEM 55296

__global__ void __launch_bounds__(128) attn_kernel(const float* __restrict__ mask)
{
    extern __shared__ char sm[];
    uint32_t sb = smem_u32(sm);
    int b = blockIdx.x, h = blockIdx.y;
    int tid = threadIdx.x, wid = tid >> 5, lane = tid & 31;

    #pragma unroll 4
    for (int i = tid; i < ATTN_SMEM / 16; i += 128)
        ((uint4*)sm)[i] = make_uint4(0u, 0u, 0u, 0u);
    __syncthreads();

    const float* base = g_qkv + (size_t)b * 49 * 1536 + h * 64;

    for (int t = tid; t < 1568; t += 128) {
        int ten = (t >= 784) ? 1 : 0;
        int rem = t - ten * 784;
        int row = rem >> 4, c4 = rem & 15;
        float4 v = *(const float4*)(base + ten * 512 + (size_t)row * 1536 + c4 * 4);
        __nv_bfloat16 hx, lx, hy, ly, hz, lz, hw, lw;
        split_bf16(v.x, hx, lx); split_bf16(v.y, hy, ly);
        split_bf16(v.z, hz, lz); split_bf16(v.w, hw, lw);
        char* dh = sm + (ten ? AT_KH : AT_QH) + row * 144 + c4 * 8;
        char* dl = sm + (ten ? AT_KL : AT_QL) + row * 144 + c4 * 8;
        ((uint32_t*)dh)[0] = pack2(hx, hy); ((uint32_t*)dh)[1] = pack2(hz, hw);
        ((uint32_t*)dl)[0] = pack2(lx, ly); ((uint32_t*)dl)[1] = pack2(lz, lw);
    }
    for (int t = tid; t < 784; t += 128) {
        int row = t >> 4, c4 = t & 15;
        float4 v = *(const float4*)(base + 1024 + (size_t)row * 1536 + c4 * 4);
        float vv[4] = {v.x, v.y, v.z, v.w};
        #pragma unroll
        for (int i = 0; i < 4; ++i) {
            int d = c4 * 4 + i;
            __nv_bfloat16 hh, ll; split_bf16(vv[i], hh, ll);
            *(__nv_bfloat16*)(sm + AT_VH + d * 144 + row * 2) = hh;
            *(__nv_bfloat16*)(sm + AT_VL + d * 144 + row * 2) = ll;
        }
    }
    __syncthreads();

    uint32_t aoff = (uint32_t)((wid * 16 + (lane & 15)) * 144 + (lane >> 4) * 16);
    uint32_t boff = (uint32_t)(((((lane >> 4) << 3)) + (lane & 7)) * 144
                               + (((lane >> 3) & 1) << 4));

    float qa[8][4];
    #pragma unroll
    for (int ni = 0; ni < 8; ++ni)
        #pragma unroll
        for (int e = 0; e < 4; ++e) qa[ni][e] = 0.f;

    #pragma unroll
    for (int ks = 0; ks < 4; ++ks) {
        uint32_t kb = (uint32_t)(ks * 32);
        uint32_t bh[16], bl[16], ah[4], al[4];
        #pragma unroll
        for (int nb = 0; nb < 4; ++nb) {
            LDMX4(bh[4*nb], bh[4*nb+1], bh[4*nb+2], bh[4*nb+3],
                  sb + AT_KH + boff + kb + (uint32_t)(nb * 16 * 144));
            LDMX4(bl[4*nb], bl[4*nb+1], bl[4*nb+2], bl[4*nb+3],
                  sb + AT_KL + boff + kb + (uint32_t)(nb * 16 * 144));
        }
        LDMX4(ah[0], ah[1], ah[2], ah[3], sb + AT_QH + aoff + kb);
        LDMX4(al[0], al[1], al[2], al[3], sb + AT_QL + aoff + kb);
        #pragma unroll
        for (int ni = 0; ni < 8; ++ni) {
            MMA16816BF(qa[ni], ah, bh[2 * ni], bh[2 * ni + 1]);
            MMA16816BF(qa[ni], ah, bl[2 * ni], bl[2 * ni + 1]);
            MMA16816BF(qa[ni], al, bh[2 * ni], bh[2 * ni + 1]);
        }
    }

    int r0 = wid * 16 + (lane >> 2), r1 = r0 + 8;
    const float* mb = mask + (size_t)(b & 255) * 2401;
    #pragma unroll
    for (int ni = 0; ni < 8; ++ni) {
        int c = ni * 8 + (lane & 3) * 2;
        if (r0 < 49) {
            if (c < 49)     qa[ni][0] = qa[ni][0] * 0.125f + mb[r0 * 49 + c];
            else            qa[ni][0] = -1e30f;
            if (c + 1 < 49) qa[ni][1] = qa[ni][1] * 0.125f + mb[r0 * 49 + c + 1];
            else            qa[ni][1] = -1e30f;
        } else {
            qa[ni][0] = (c < 49) ? 0.f : -1e30f;
            qa[ni][1] = (c + 1 < 49) ? 0.f : -1e30f;
        }
        if (r1 < 49) {
            if (c < 49)     qa[ni][2] = qa[ni][2] * 0.125f + mb[r1 * 49 + c];
            else            qa[ni][2] = -1e30f;
            if (c + 1 < 49) qa[ni][3] = qa[ni][3] * 0.125f + mb[r1 * 49 + c + 1];
            else            qa[ni][3] = -1e30f;
        } else {
            qa[ni][2] = (c < 49) ? 0.f : -1e30f;
            qa[ni][3] = (c + 1 < 49) ? 0.f : -1e30f;
        }
    }
    float mx0 = -1e30f, mx1 = -1e30f;
    #pragma unroll
    for (int ni = 0; ni < 8; ++ni) {
        mx0 = fmaxf(mx0, fmaxf(qa[ni][0], qa[ni][1]));
        mx1 = fmaxf(mx1, fmaxf(qa[ni][2], qa[ni][3]));
    }
    mx0 = fmaxf(mx0, __shfl_xor_sync(0xFFFFFFFFu, mx0, 1));
    mx0 = fmaxf(mx0, __shfl_xor_sync(0xFFFFFFFFu, mx0, 2));
    mx1 = fmaxf(mx1, __shfl_xor_sync(0xFFFFFFFFu, mx1, 1));
    mx1 = fmaxf(mx1, __shfl_xor_sync(0xFFFFFFFFu, mx1, 2));
    float s0 = 0.f, s1 = 0.f;
    #pragma unroll
    for (int ni = 0; ni < 8; ++ni) {
        qa[ni][0] = __expf(qa[ni][0] - mx0); s0 += qa[ni][0];
        qa[ni][1] = __expf(qa[ni][1] - mx0); s0 += qa[ni][1];
        qa[ni][2] = __expf(qa[ni][2] - mx1); s1 += qa[ni][2];
        qa[ni][3] = __expf(qa[ni][3] - mx1); s1 += qa[ni][3];
    }
    s0 += __shfl_xor_sync(0xFFFFFFFFu, s0, 1);
    s0 += __shfl_xor_sync(0xFFFFFFFFu, s0, 2);
    s1 += __shfl_xor_sync(0xFFFFFFFFu, s1, 1);
    s1 += __shfl_xor_sync(0xFFFFFFFFu, s1, 2);
    float i0 = __fdividef(1.f, s0), i1 = __fdividef(1.f, s1);
    #pragma unroll
    for (int ni = 0; ni < 8; ++ni) {
        qa[ni][0] *= i0; qa[ni][1] *= i0;
        qa[ni][2] *= i1; qa[ni][3] *= i1;
    }

    float oa[8][4];
    #pragma unroll
    for (int ni = 0; ni < 8; ++ni)
        #pragma unroll
        for (int e = 0; e < 4; ++e) oa[ni][e] = 0.f;

    #pragma unroll
    for (int kk = 0; kk < 4; ++kk) {
        int n0i = 2 * kk, n1i = 2 * kk + 1;
        uint32_t ah[4], al[4];
        {
            __nv_bfloat16 ha, la, hb, lb;
            split_bf16(qa[n0i][0], ha, la); split_bf16(qa[n0i][1], hb, lb);
            ah[0] = pack2(ha, hb); al[0] = pack2(la, lb);
            split_bf16(qa[n0i][2], ha, la); split_bf16(qa[n0i][3], hb, lb);
            ah[1] = pack2(ha, hb); al[1] = pack2(la, lb);
            split_bf16(qa[n1i][0], ha, la); split_bf16(qa[n1i][1], hb, lb);
            ah[2] = pack2(ha, hb); al[2] = pack2(la, lb);
            split_bf16(qa[n1i][2], ha, la); split_bf16(qa[n1i][3], hb, lb);
            ah[3] = pack2(ha, hb); al[3] = pack2(la, lb);
        }
        uint32_t kb = (uint32_t)(kk * 32);
        uint32_t bvh[16], bvl[16];
        #pragma unroll
        for (int nb = 0; nb < 4; ++nb) {
            LDMX4(bvh[4*nb], bvh[4*nb+1], bvh[4*nb+2], bvh[4*nb+3],
                  sb + AT_VH + boff + kb + (uint32_t)(nb * 16 * 144));
            LDMX4(bvl[4*nb], bvl[4*nb+1], bvl[4*nb+2], bvl[4*nb+3],
                  sb + AT_VL + boff + kb + (uint32_t)(nb * 16 * 144));
        }
        #pragma unroll
        for (int ni = 0; ni < 8; ++ni) {
            MMA16816BF(oa[ni], ah, bvh[2 * ni], bvh[2 * ni + 1]);
            MMA16816BF(oa[ni], ah, bvl[2 * ni], bvl[2 * ni + 1]);
            MMA16816BF(oa[ni], al, bvh[2 * ni], bvh[2 * ni + 1]);
        }
    }

    // store as plain fp16 for 1-pass GEMM2
    #pragma unroll
    for (int ni = 0; ni < 8; ++ni) {
        int c = ni * 8 + (lane & 3) * 2;
        if (r0 < 49) {
            size_t o = ((size_t)b * 49 + r0) * 512 + h * 64 + c;
            *(uint32_t*)&g_att[o] = pack2h(__float2half_rn(oa[ni][0]),
                                           __float2half_rn(oa[ni][1]));
        }
        if (r1 < 49) {
            size_t o = ((size_t)b * 49 + r1) * 512 + h * 64 + c;
            *(uint32_t*)&g_att[o] = pack2h(__float2half_rn(oa[ni][2]),
                                           __float2half_rn(oa[ni][3]));
        }
    }
}

// ============================================================================
// launch
// ============================================================================
extern "C" void kernel_launch(void* const* d_in, const int* in_sizes, int n_in,
                              void* d_out, int out_size)
{
    const float* x    = (const float*)d_in[0];
    const float* mask = (const float*)d_in[1];
    const float* Wq   = (const float*)d_in[2];
    const float* bq   = (const float*)d_in[3];
    const float* Wk   = (const float*)d_in[4];
    const float* bk   = (const float*)d_in[5];
    const float* Wv   = (const float*)d_in[6];
    const float* bv   = (const float*)d_in[7];
    const float* Wp   = (const float*)d_in[8];
    const float* bp   = (const float*)d_in[9];
    float* out = (float*)d_out;

    cudaFuncSetAttribute(gemm_kernel,
                         cudaFuncAttributeMaxDynamicSharedMemorySize, GEMM_SMEM);
    cudaFuncSetAttribute(attn_kernel,
                         cudaFuncAttributeMaxDynamicSharedMemorySize, ATTN_SMEM);

    __half *xh, *wqkv, *wp, *att;
    float *qkv, *bqkv;
    cudaGetSymbolAddress((void**)&xh,   g_x);
    cudaGetSymbolAddress((void**)&wqkv, g_wqkv);
    cudaGetSymbolAddress((void**)&wp,   g_wp);
    cudaGetSymbolAddress((void**)&att,  g_att);
    cudaGetSymbolAddress((void**)&qkv,  g_qkv);
    cudaGetSymbolAddress((void**)&bqkv, g_bqkv);

    prep_w_kernel<<<1024, 256>>>(Wq, Wk, Wv, bq, bk, bv, Wp);
    prep_x_kernel<<<8192, 256>>>(x);

    // GEMM1a: Q|K columns (n 0..1023), full K=1024 -> 4 n-tiles of 256, kc=8
    gemm_kernel<<<784 * 4, 256, GEMM_SMEM>>>(
        xh, K_QKV, wqkv, K_QKV, bqkv, qkv, N_QKV, 4, 8);

    // GEMM1b: V columns (n 1024..1535), real K=512 -> 2 n-tiles of 256, kc=4
    gemm_kernel<<<784 * 2, 256, GEMM_SMEM>>>(
        xh, K_QKV,
        wqkv + (size_t)1024 * K_QKV, K_QKV,
        bqkv + 1024, qkv + 1024, N_QKV, 2, 4);

    // attention (reads g_qkv, writes g_att fp16) — HMMA path
    attn_kernel<<<dim3(2048, 8), 128, ATTN_SMEM>>>(mask);

    // GEMM2: out = att @ Wp + bp    (M=100352, K=512, N=1024) -> 4 n-tiles, kc=4
    gemm_kernel<<<784 * 4, 256, GEMM_SMEM>>>(
        att, K_PROJ, wp, K_PROJ, bp, out, N_PROJ, 4, 4);
}

// round 16
// speedup vs baseline: 1.7202x; 1.7202x over previous
#include <cuda_runtime.h>
#include <cuda_bf16.h>
#include <cuda_fp16.h>
#include <stdint.h>
#include <stddef.h>

// ============================================================================
// WindowAttention on sm_103 (baseline ISA: mma.sync HMMA, cp.async, ldmatrix)
//   qkv = x @ [Wq|Wk|Wv] + b      (M=100352, K=1024, N=1536, Wv zero-padded)
//   attn = softmax(q k^T * 0.125 + mask[b%256]) ; att = attn @ v
//   out  = att @ Wp + bp          (M=100352, K=512,  N=1024)
// R15: GEMM mainloop = R13 verbatim (fastest known; R14 frag-pipeline spilled).
//      qkv intermediate now fp16 -> attention runs pure fp16 1-pass HMMA
//      (inputs already fp16 => no extra rounding; only P->fp16 adds ~2.4e-4).
//      Predicted rel_err ~7e-4 vs 1e-3 gate.
// ============================================================================

#define M_ROWS   100352
#define N_QKV    1536
#define K_QKV    1024
#define N_PROJ   1024
#define K_PROJ   512

// ---------------- scratch (device globals; no allocation allowed) -----------
__device__ __align__(16) __half  g_qkv[(size_t)M_ROWS * N_QKV];
__device__ __align__(16) __half  g_x[(size_t)M_ROWS * K_QKV];
__device__ __align__(16) __half  g_att[(size_t)M_ROWS * K_PROJ];
__device__ __align__(16) __half  g_wqkv[(size_t)N_QKV * K_QKV];
__device__ __align__(16) __half  g_wp[(size_t)N_PROJ * K_PROJ];
__device__ float g_bqkv[N_QKV];

// ---------------- helpers ----------------------------------------------------
__device__ __forceinline__ uint32_t smem_u32(const void* p) {
    uint32_t a;
    asm("{ .reg .u64 t; cvta.to.shared.u64 t, %1; cvt.u32.u64 %0, t; }"
        : "=r"(a) : "l"(p));
    return a;
}
__device__ __forceinline__ uint32_t pack2h(__half a, __half b) {
    return ((uint32_t)__half_as_ushort(b) << 16) | (uint32_t)__half_as_ushort(a);
}

#define CP16(dst, src) \
    asm volatile("cp.async.cg.shared.global [%0], [%1], 16;" \
                 :: "r"(dst), "l"(src))
#define CP_COMMIT() asm volatile("cp.async.commit_group;" ::: "memory")
#define CP_WAIT0()  asm volatile("cp.async.wait_group 0;" ::: "memory")
#define CP_WAIT1()  asm volatile("cp.async.wait_group 1;" ::: "memory")

#define LDMX4(r0, r1, r2, r3, addr) \
    asm volatile("ldmatrix.sync.aligned.m8n8.x4.shared.b16 {%0,%1,%2,%3}, [%4];" \
                 : "=r"(r0), "=r"(r1), "=r"(r2), "=r"(r3) : "r"(addr))

#define MMA16816H(d, a, b0, b1) \
    asm volatile("mma.sync.aligned.m16n8k16.row.col.f32.f16.f16.f32 " \
                 "{%0,%1,%2,%3}, {%4,%5,%6,%7}, {%8,%9}, {%0,%1,%2,%3};" \
                 : "+f"((d)[0]), "+f"((d)[1]), "+f"((d)[2]), "+f"((d)[3]) \
                 : "r"((a)[0]), "r"((a)[1]), "r"((a)[2]), "r"((a)[3]), \
                   "r"(b0), "r"(b1))

// ============================================================================
// prep: weights (transposed, fused, fp16) + bias
// ============================================================================
__global__ void prep_w_kernel(const float* __restrict__ Wq, const float* __restrict__ Wk,
                              const float* __restrict__ Wv, const float* __restrict__ bq,
                              const float* __restrict__ bk, const float* __restrict__ bv,
                              const float* __restrict__ Wp)
{
    const int T1 = N_QKV * K_QKV;
    const int T2 = N_PROJ * K_PROJ;
    const int TOT = T1 + T2 + N_QKV;
    int stride = gridDim.x * blockDim.x;
    for (int idx = blockIdx.x * blockDim.x + threadIdx.x; idx < TOT; idx += stride) {
        if (idx < T1) {
            int n = idx >> 10, k = idx & 1023;
            float w;
            if (n < 512)       w = Wq[k * 512 + n];
            else if (n < 1024) w = Wk[k * 512 + (n - 512)];
            else               w = (k < 512) ? Wv[k * 512 + (n - 1024)] : 0.f;
            g_wqkv[idx] = __float2half_rn(w);
        } else if (idx < T1 + T2) {
            int i = idx - T1;
            int n = i >> 9, k = i & 511;
            g_wp[i] = __float2half_rn(Wp[k * 1024 + n]);
        } else {
            int n = idx - T1 - T2;
            g_bqkv[n] = (n < 512) ? bq[n] : (n < 1024) ? bk[n - 512] : bv[n - 1024];
        }
    }
}

// x[M][1024] f32 -> fp16
__global__ void prep_x_kernel(const float* __restrict__ x)
{
    const size_t TOT = (size_t)M_ROWS * K_QKV / 8;
    size_t stride = (size_t)gridDim.x * blockDim.x;
    for (size_t t = blockIdx.x * (size_t)blockDim.x + threadIdx.x; t < TOT; t += stride) {
        const float4* src = (const float4*)(x + t * 8);
        float4 f0 = src[0], f1 = src[1];
        float v[8] = {f0.x, f0.y, f0.z, f0.w, f1.x, f1.y, f1.z, f1.w};
        __half h[8];
        #pragma unroll
        for (int e = 0; e < 8; ++e) h[e] = __float2half_rn(v[e]);
        *(uint4*)(g_x + t * 8) = *(uint4*)h;
    }
}

// ============================================================================
// 1-pass fp16 GEMM (R13 mainloop verbatim): C = fp16(A) @ fp16(B)^T + bias
//   CTA tile 128x256, K-chunk 128, 8 warps (2x4 -> warp tile 64x64)
//   Epilogue templated: fp32 output (final) or fp16 output (qkv intermediate).
// ============================================================================
#define ROWB    272                 // padded row bytes (136 fp16; 128 data)
#define ARRB_A  34816               // 128*272
#define ARRB_B  69632               // 256*272
#define OFF_B   34816
#define STAGEB  104448              // ARRB_A + ARRB_B
#define GEMM_SMEM (2 * STAGEB)      // 208896

template <bool OUT_HALF>
__global__ void __launch_bounds__(256, 1) gemm_kernel(
    const __half* __restrict__ A, int lda,
    const __half* __restrict__ B, int ldb,
    const float* __restrict__ bias,
    void* __restrict__ Cv, int ldc,
    int n_tiles, int k_chunks)
{
    extern __shared__ char smem[];
    uint32_t sbase = smem_u32(smem);
    int tid = threadIdx.x, wid = tid >> 5, lane = tid & 31;
    int nt = blockIdx.x % n_tiles, mt = blockIdx.x / n_tiles;
    int m0 = mt * 128, n0 = nt * 256;

    int warp_m = (wid >> 2) * 64;         // 0 or 64
    int warp_n = (wid & 3) * 64;          // 0,64,128,192

    uint32_t aoff = (uint32_t)((warp_m + (lane & 15)) * ROWB + (lane >> 4) * 16);
    uint32_t boff = (uint32_t)((warp_n + ((lane >> 4) << 3) + (lane & 7)) * ROWB
                               + (((lane >> 3) & 1) << 4));

    float acc[4][8][4];
    #pragma unroll
    for (int i = 0; i < 4; ++i)
        #pragma unroll
        for (int j = 0; j < 8; ++j)
            #pragma unroll
            for (int e = 0; e < 4; ++e) acc[i][j][e] = 0.f;

    auto load_chunk = [&](int c) {
        uint32_t sb = sbase + (uint32_t)(c & 1) * STAGEB;
        const __half* Ap = A + (size_t)m0 * lda + c * 128;
        const __half* Bp = B + (size_t)n0 * ldb + c * 128;
        #pragma unroll
        for (int q = 0; q < 8; ++q) {
            int t = tid + q * 256;
            int r = t >> 4, j = t & 15;
            uint32_t dst = sb + (uint32_t)(r * ROWB + j * 16);
            const void* src = Ap + (size_t)r * lda + j * 8;
            CP16(dst, src);
        }
        #pragma unroll
        for (int q = 0; q < 16; ++q) {
            int t = tid + q * 256;
            int r = (t >> 4) & 255, j = t & 15;
            uint32_t dst = sb + OFF_B + (uint32_t)(r * ROWB + j * 16);
            const void* src = Bp + (size_t)r * ldb + j * 8;
            CP16(dst, src);
        }
    };

    load_chunk(0);
    CP_COMMIT();

    for (int c = 0; c < k_chunks; ++c) {
        if (c + 1 < k_chunks) { load_chunk(c + 1); CP_COMMIT(); CP_WAIT1(); }
        else                  { CP_WAIT0(); }
        __syncthreads();

        uint32_t sb = sbase + (uint32_t)(c & 1) * STAGEB;
        uint32_t sA = sb + aoff;
        uint32_t sB = sb + OFF_B + boff;

        #pragma unroll
        for (int ks = 0; ks < 8; ++ks) {
            uint32_t kb = (uint32_t)(ks * 32);
            uint32_t bh[16];
            #pragma unroll
            for (int nb = 0; nb < 4; ++nb) {
                LDMX4(bh[4*nb], bh[4*nb+1], bh[4*nb+2], bh[4*nb+3],
                      sB + kb + (uint32_t)(nb * 16 * ROWB));
            }
            #pragma unroll
            for (int mi = 0; mi < 4; ++mi) {
                uint32_t ah[4];
                LDMX4(ah[0], ah[1], ah[2], ah[3], sA + kb + (uint32_t)(mi * 16 * ROWB));
                #pragma unroll
                for (int ni = 0; ni < 8; ++ni) {
                    MMA16816H(acc[mi][ni], ah, bh[2 * ni], bh[2 * ni + 1]);
                }
            }
        }
        __syncthreads();
    }

    #pragma unroll
    for (int mi = 0; mi < 4; ++mi) {
        int m = m0 + warp_m + mi * 16 + (lane >> 2);
        #pragma unroll
        for (int ni = 0; ni < 8; ++ni) {
            int n = n0 + warp_n + ni * 8 + (lane & 3) * 2;
            float b0 = bias[n], b1 = bias[n + 1];
            float v00 = acc[mi][ni][0] + b0, v01 = acc[mi][ni][1] + b1;
            float v10 = acc[mi][ni][2] + b0, v11 = acc[mi][ni][3] + b1;
            if (OUT_HALF) {
                __half* Ch = (__half*)Cv;
                *(uint32_t*)(Ch + (size_t)m * ldc + n) =
                    pack2h(__float2half_rn(v00), __float2half_rn(v01));
                *(uint32_t*)(Ch + (size_t)(m + 8) * ldc + n) =
                    pack2h(__float2half_rn(v10), __float2half_rn(v11));
            } else {
                float* Cf = (float*)Cv;
                *(float2*)(Cf + (size_t)m * ldc + n) = make_float2(v00, v01);
                *(float2*)(Cf + (size_t)(m + 8) * ldc + n) = make_float2(v10, v11);
            }
        }
    }
}

// ============================================================================
// fp16 HMMA attention: CTA per (window b, head h), 4 warps, 1-pass fp16.
// qkv is fp16 -> QK and PV add no input rounding; P->fp16 only new term.
// smem: Q[64x144B] K[64x144B] VT[64x144B] = 27648 B
// ============================================================================
#define AT_Q  0
#define AT_K  9216
#define AT_V  18432
#define ATTN_SMEM 27648

__global__ void __launch_bounds__(128) attn_kernel(const float* __restrict__ mask)
{
    extern __shared__ char sm[];
    uint32_t sb = smem_u32(sm);
    int b = blockIdx.x, h = blockIdx.y;
    int tid = threadIdx.x, wid = tid >> 5, lane = tid & 31;

    // zero all (pad rows/cols must be 0)
    for (int i = tid; i < ATTN_SMEM / 16; i += 128)
        ((uint4*)sm)[i] = make_uint4(0u, 0u, 0u, 0u);
    __syncthreads();

    const __half* base = g_qkv + (size_t)b * 49 * 1536 + h * 64;

    // Q,K: 49 rows x 8 uint4 each
    for (int t = tid; t < 2 * 392; t += 128) {
        int ten = (t >= 392) ? 1 : 0;
        int rem = t - ten * 392;
        int row = rem >> 3, c8 = rem & 7;
        uint4 v = *(const uint4*)(base + ten * 512 + (size_t)row * 1536 + c8 * 8);
        *(uint4*)(sm + (ten ? AT_K : AT_Q) + row * 144 + c8 * 16) = v;
    }
    // V transposed: VT[d][token]
    for (int t = tid; t < 392; t += 128) {
        int row = t >> 3, c8 = t & 7;
        uint4 v = *(const uint4*)(base + 1024 + (size_t)row * 1536 + c8 * 8);
        const __half* hv = (const __half*)&v;
        #pragma unroll
        for (int i = 0; i < 8; ++i) {
            int d = c8 * 8 + i;
            *(__half*)(sm + AT_V + d * 144 + row * 2) = hv[i];
        }
    }
    __syncthreads();

    uint32_t aoff = (uint32_t)((wid * 16 + (lane & 15)) * 144 + (lane >> 4) * 16);
    uint32_t boff = (uint32_t)(((((lane >> 4) << 3)) + (lane & 7)) * 144
                               + (((lane >> 3) & 1) << 4));

    // ---- QK^T (1-pass fp16) ----
    float qa[8][4];
    #pragma unroll
    for (int ni = 0; ni < 8; ++ni)
        #pragma unroll
        for (int e = 0; e < 4; ++e) qa[ni][e] = 0.f;

    #pragma unroll
    for (int ks = 0; ks < 4; ++ks) {
        uint32_t kb = (uint32_t)(ks * 32);
        uint32_t bh[16], ah[4];
        #pragma unroll
        for (int nb = 0; nb < 4; ++nb)
            LDMX4(bh[4*nb], bh[4*nb+1], bh[4*nb+2], bh[4*nb+3],
                  sb + AT_K + boff + kb + (uint32_t)(nb * 16 * 144));
        LDMX4(ah[0], ah[1], ah[2], ah[3], sb + AT_Q + aoff + kb);
        #pragma unroll
        for (int ni = 0; ni < 8; ++ni)
            MMA16816H(qa[ni], ah, bh[2 * ni], bh[2 * ni + 1]);
    }

    // ---- mask + softmax in registers ----
    int r0 = wid * 16 + (lane >> 2), r1 = r0 + 8;
    const float* mb = mask + (size_t)(b & 255) * 2401;
    #pragma unroll
    for (int ni = 0; ni < 8; ++ni) {
        int c = ni * 8 + (lane & 3) * 2;
        if (r0 < 49) {
            if (c < 49)     qa[ni][0] = qa[ni][0] * 0.125f + mb[r0 * 49 + c];
            else            qa[ni][0] = -1e30f;
            if (c + 1 < 49) qa[ni][1] = qa[ni][1] * 0.125f + mb[r0 * 49 + c + 1];
            else            qa[ni][1] = -1e30f;
        } else {
            qa[ni][0] = (c < 49) ? 0.f : -1e30f;
            qa[ni][1] = (c + 1 < 49) ? 0.f : -1e30f;
        }
        if (r1 < 49) {
            if (c < 49)     qa[ni][2] = qa[ni][2] * 0.125f + mb[r1 * 49 + c];
            else            qa[ni][2] = -1e30f;
            if (c + 1 < 49) qa[ni][3] = qa[ni][3] * 0.125f + mb[r1 * 49 + c + 1];
            else            qa[ni][3] = -1e30f;
        } else {
            qa[ni][2] = (c < 49) ? 0.f : -1e30f;
            qa[ni][3] = (c + 1 < 49) ? 0.f : -1e30f;
        }
    }
    float mx0 = -1e30f, mx1 = -1e30f;
    #pragma unroll
    for (int ni = 0; ni < 8; ++ni) {
        mx0 = fmaxf(mx0, fmaxf(qa[ni][0], qa[ni][1]));
        mx1 = fmaxf(mx1, fmaxf(qa[ni][2], qa[ni][3]));
    }
    mx0 = fmaxf(mx0, __shfl_xor_sync(0xFFFFFFFFu, mx0, 1));
    mx0 = fmaxf(mx0, __shfl_xor_sync(0xFFFFFFFFu, mx0, 2));
    mx1 = fmaxf(mx1, __shfl_xor_sync(0xFFFFFFFFu, mx1, 1));
    mx1 = fmaxf(mx1, __shfl_xor_sync(0xFFFFFFFFu, mx1, 2));
    float s0 = 0.f, s1 = 0.f;
    #pragma unroll
    for (int ni = 0; ni < 8; ++ni) {
        qa[ni][0] = __expf(qa[ni][0] - mx0); s0 += qa[ni][0];
        qa[ni][1] = __expf(qa[ni][1] - mx0); s0 += qa[ni][1];
        qa[ni][2] = __expf(qa[ni][2] - mx1); s1 += qa[ni][2];
        qa[ni][3] = __expf(qa[ni][3] - mx1); s1 += qa[ni][3];
    }
    s0 += __shfl_xor_sync(0xFFFFFFFFu, s0, 1);
    s0 += __shfl_xor_sync(0xFFFFFFFFu, s0, 2);
    s1 += __shfl_xor_sync(0xFFFFFFFFu, s1, 1);
    s1 += __shfl_xor_sync(0xFFFFFFFFu, s1, 2);
    float i0 = __fdividef(1.f, s0), i1 = __fdividef(1.f, s1);
    #pragma unroll
    for (int ni = 0; ni < 8; ++ni) {
        qa[ni][0] *= i0; qa[ni][1] *= i0;
        qa[ni][2] *= i1; qa[ni][3] *= i1;
    }

    // ---- P @ V (1-pass fp16; P A-frags packed from C-frags) ----
    float oa[8][4];
    #pragma unroll
    for (int ni = 0; ni < 8; ++ni)
        #pragma unroll
        for (int e = 0; e < 4; ++e) oa[ni][e] = 0.f;

    #pragma unroll
    for (int kk = 0; kk < 4; ++kk) {
        int n0i = 2 * kk, n1i = 2 * kk + 1;
        uint32_t ah[4];
        ah[0] = pack2h(__float2half_rn(qa[n0i][0]), __float2half_rn(qa[n0i][1]));
        ah[1] = pack2h(__float2half_rn(qa[n0i][2]), __float2half_rn(qa[n0i][3]));
        ah[2] = pack2h(__float2half_rn(qa[n1i][0]), __float2half_rn(qa[n1i][1]));
        ah[3] = pack2h(__float2half_rn(qa[n1i][2]), __float2half_rn(qa[n1i][3]));
        uint32_t kb = (uint32_t)(kk * 32);
        uint32_t bv[16];
        #pragma unroll
        for (int nb = 0; nb < 4; ++nb)
            LDMX4(bv[4*nb], bv[4*nb+1], bv[4*nb+2], bv[4*nb+3],
                  sb + AT_V + boff + kb + (uint32_t)(nb * 16 * 144));
        #pragma unroll
        for (int ni = 0; ni < 8; ++ni)
            MMA16816H(oa[ni], ah, bv[2 * ni], bv[2 * ni + 1]);
    }

    // ---- store fp16 ----
    #pragma unroll
    for (int ni = 0; ni < 8; ++ni) {
        int c = ni * 8 + (lane & 3) * 2;
        if (r0 < 49) {
            size_t o = ((size_t)b * 49 + r0) * 512 + h * 64 + c;
            *(uint32_t*)&g_att[o] = pack2h(__float2half_rn(oa[ni][0]),
                                           __float2half_rn(oa[ni][1]));
        }
        if (r1 < 49) {
            size_t o = ((size_t)b * 49 + r1) * 512 + h * 64 + c;
            *(uint32_t*)&g_att[o] = pack2h(__float2half_rn(oa[ni][2]),
                                           __float2half_rn(oa[ni][3]));
        }
    }
}

// ============================================================================
// launch
// ============================================================================
extern "C" void kernel_launch(void* const* d_in, const int* in_sizes, int n_in,
                              void* d_out, int out_size)
{
    const float* x    = (const float*)d_in[0];
    const float* mask = (const float*)d_in[1];
    const float* Wq   = (const float*)d_in[2];
    const float* bq   = (const float*)d_in[3];
    const float* Wk   = (const float*)d_in[4];
    const float* bk   = (const float*)d_in[5];
    const float* Wv   = (const float*)d_in[6];
    const float* bv   = (const float*)d_in[7];
    const float* Wp   = (const float*)d_in[8];
    const float* bp   = (const float*)d_in[9];
    float* out = (float*)d_out;

    cudaFuncSetAttribute(gemm_kernel<true>,
                         cudaFuncAttributeMaxDynamicSharedMemorySize, GEMM_SMEM);
    cudaFuncSetAttribute(gemm_kernel<false>,
                         cudaFuncAttributeMaxDynamicSharedMemorySize, GEMM_SMEM);
    cudaFuncSetAttribute(attn_kernel,
                         cudaFuncAttributeMaxDynamicSharedMemorySize, ATTN_SMEM);

    __half *xh, *wqkv, *wp, *att, *qkv;
    float *bqkv;
    cudaGetSymbolAddress((void**)&xh,   g_x);
    cudaGetSymbolAddress((void**)&wqkv, g_wqkv);
    cudaGetSymbolAddress((void**)&wp,   g_wp);
    cudaGetSymbolAddress((void**)&att,  g_att);
    cudaGetSymbolAddress((void**)&qkv,  g_qkv);
    cudaGetSymbolAddress((void**)&bqkv, g_bqkv);

    prep_w_kernel<<<1024, 256>>>(Wq, Wk, Wv, bq, bk, bv, Wp);
    prep_x_kernel<<<8192, 256>>>(x);

    // GEMM1a: Q|K columns (n 0..1023), full K=1024 -> 4 n-tiles of 256, kc=8
    gemm_kernel<true><<<784 * 4, 256, GEMM_SMEM>>>(
        xh, K_QKV, wqkv, K_QKV, bqkv, qkv, N_QKV, 4, 8);

    // GEMM1b: V columns (n 1024..1535), real K=512 -> 2 n-tiles of 256, kc=4
    gemm_kernel<true><<<784 * 2, 256, GEMM_SMEM>>>(
        xh, K_QKV,
        wqkv + (size_t)1024 * K_QKV, K_QKV,
        bqkv + 1024, qkv + 1024, N_QKV, 2, 4);

    // attention (reads g_qkv fp16, writes g_att fp16)
    attn_kernel<<<dim3(2048, 8), 128, ATTN_SMEM>>>(mask);

    // GEMM2: out = att @ Wp + bp    (M=100352, K=512, N=1024) -> 4 n-tiles, kc=4
    gemm_kernel<false><<<784 * 4, 256, GEMM_SMEM>>>(
        att, K_PROJ, wp, K_PROJ, bp, out, N_PROJ, 4, 4);
}

// round 17
// speedup vs baseline: 1.7223x; 1.0012x over previous
#include <cuda_runtime.h>
#include <cuda_bf16.h>
#include <cuda_fp16.h>
#include <stdint.h>
#include <stddef.h>

// ============================================================================
// WindowAttention on sm_103 (baseline ISA: mma.sync HMMA, cp.async, ldmatrix)
//   qkv = x @ [Wq|Wk|Wv] + b      (M=100352, K=1024, N=1536, Wv zero-padded)
//   attn = softmax(q k^T * 0.125 + mask[b%256]) ; att = attn @ v
//   out  = att @ Wp + bp          (M=100352, K=512,  N=1024)
// R16: gemm inner loop restructured — ALL 4 A-frag LDMX4 of a ks step hoisted
//      ahead of the 32 MMAs (flat ah[16], +12 regs) so each A-LDSM's ~30cyc
//      latency is covered by subsequent LDSM issue instead of stalling the
//      first HMMA of its mi group (R15: tensor 45.6%, latency-bound).
// GEMMs 1-pass fp16 (rel_err 6.6e-4 vs 1e-3); attention pure fp16 HMMA.
// ============================================================================

#define M_ROWS   100352
#define N_QKV    1536
#define K_QKV    1024
#define N_PROJ   1024
#define K_PROJ   512

// ---------------- scratch (device globals; no allocation allowed) -----------
__device__ __align__(16) __half  g_qkv[(size_t)M_ROWS * N_QKV];
__device__ __align__(16) __half  g_x[(size_t)M_ROWS * K_QKV];
__device__ __align__(16) __half  g_att[(size_t)M_ROWS * K_PROJ];
__device__ __align__(16) __half  g_wqkv[(size_t)N_QKV * K_QKV];
__device__ __align__(16) __half  g_wp[(size_t)N_PROJ * K_PROJ];
__device__ float g_bqkv[N_QKV];

// ---------------- helpers ----------------------------------------------------
__device__ __forceinline__ uint32_t smem_u32(const void* p) {
    uint32_t a;
    asm("{ .reg .u64 t; cvta.to.shared.u64 t, %1; cvt.u32.u64 %0, t; }"
        : "=r"(a) : "l"(p));
    return a;
}
__device__ __forceinline__ uint32_t pack2h(__half a, __half b) {
    return ((uint32_t)__half_as_ushort(b) << 16) | (uint32_t)__half_as_ushort(a);
}

#define CP16(dst, src) \
    asm volatile("cp.async.cg.shared.global [%0], [%1], 16;" \
                 :: "r"(dst), "l"(src))
#define CP_COMMIT() asm volatile("cp.async.commit_group;" ::: "memory")
#define CP_WAIT0()  asm volatile("cp.async.wait_group 0;" ::: "memory")
#define CP_WAIT1()  asm volatile("cp.async.wait_group 1;" ::: "memory")

#define LDMX4(r0, r1, r2, r3, addr) \
    asm volatile("ldmatrix.sync.aligned.m8n8.x4.shared.b16 {%0,%1,%2,%3}, [%4];" \
                 : "=r"(r0), "=r"(r1), "=r"(r2), "=r"(r3) : "r"(addr))

#define MMA16816H(d, a, b0, b1) \
    asm volatile("mma.sync.aligned.m16n8k16.row.col.f32.f16.f16.f32 " \
                 "{%0,%1,%2,%3}, {%4,%5,%6,%7}, {%8,%9}, {%0,%1,%2,%3};" \
                 : "+f"((d)[0]), "+f"((d)[1]), "+f"((d)[2]), "+f"((d)[3]) \
                 : "r"((a)[0]), "r"((a)[1]), "r"((a)[2]), "r"((a)[3]), \
                   "r"(b0), "r"(b1))

// ============================================================================
// prep: weights (transposed, fused, fp16) + bias
// ============================================================================
__global__ void prep_w_kernel(const float* __restrict__ Wq, const float* __restrict__ Wk,
                              const float* __restrict__ Wv, const float* __restrict__ bq,
                              const float* __restrict__ bk, const float* __restrict__ bv,
                              const float* __restrict__ Wp)
{
    const int T1 = N_QKV * K_QKV;
    const int T2 = N_PROJ * K_PROJ;
    const int TOT = T1 + T2 + N_QKV;
    int stride = gridDim.x * blockDim.x;
    for (int idx = blockIdx.x * blockDim.x + threadIdx.x; idx < TOT; idx += stride) {
        if (idx < T1) {
            int n = idx >> 10, k = idx & 1023;
            float w;
            if (n < 512)       w = Wq[k * 512 + n];
            else if (n < 1024) w = Wk[k * 512 + (n - 512)];
            else               w = (k < 512) ? Wv[k * 512 + (n - 1024)] : 0.f;
            g_wqkv[idx] = __float2half_rn(w);
        } else if (idx < T1 + T2) {
            int i = idx - T1;
            int n = i >> 9, k = i & 511;
            g_wp[i] = __float2half_rn(Wp[k * 1024 + n]);
        } else {
            int n = idx - T1 - T2;
            g_bqkv[n] = (n < 512) ? bq[n] : (n < 1024) ? bk[n - 512] : bv[n - 1024];
        }
    }
}

// x[M][1024] f32 -> fp16
__global__ void prep_x_kernel(const float* __restrict__ x)
{
    const size_t TOT = (size_t)M_ROWS * K_QKV / 8;
    size_t stride = (size_t)gridDim.x * blockDim.x;
    for (size_t t = blockIdx.x * (size_t)blockDim.x + threadIdx.x; t < TOT; t += stride) {
        const float4* src = (const float4*)(x + t * 8);
        float4 f0 = src[0], f1 = src[1];
        float v[8] = {f0.x, f0.y, f0.z, f0.w, f1.x, f1.y, f1.z, f1.w};
        __half h[8];
        #pragma unroll
        for (int e = 0; e < 8; ++e) h[e] = __float2half_rn(v[e]);
        *(uint4*)(g_x + t * 8) = *(uint4*)h;
    }
}

// ============================================================================
// 1-pass fp16 GEMM: C = fp16(A) @ fp16(B)^T + bias
//   CTA tile 128x256, K-chunk 128, 8 warps (2x4 -> warp tile 64x64)
//   Per-ks: all 8 LDMX4 (B then A) hoisted before the 32 MMAs.
// ============================================================================
#define ROWB    272                 // padded row bytes (136 fp16; 128 data)
#define ARRB_A  34816               // 128*272
#define ARRB_B  69632               // 256*272
#define OFF_B   34816
#define STAGEB  104448              // ARRB_A + ARRB_B
#define GEMM_SMEM (2 * STAGEB)      // 208896

template <bool OUT_HALF>
__global__ void __launch_bounds__(256, 1) gemm_kernel(
    const __half* __restrict__ A, int lda,
    const __half* __restrict__ B, int ldb,
    const float* __restrict__ bias,
    void* __restrict__ Cv, int ldc,
    int n_tiles, int k_chunks)
{
    extern __shared__ char smem[];
    uint32_t sbase = smem_u32(smem);
    int tid = threadIdx.x, wid = tid >> 5, lane = tid & 31;
    int nt = blockIdx.x % n_tiles, mt = blockIdx.x / n_tiles;
    int m0 = mt * 128, n0 = nt * 256;

    int warp_m = (wid >> 2) * 64;         // 0 or 64
    int warp_n = (wid & 3) * 64;          // 0,64,128,192

    uint32_t aoff = (uint32_t)((warp_m + (lane & 15)) * ROWB + (lane >> 4) * 16);
    uint32_t boff = (uint32_t)((warp_n + ((lane >> 4) << 3) + (lane & 7)) * ROWB
                               + (((lane >> 3) & 1) << 4));

    float acc[4][8][4];
    #pragma unroll
    for (int i = 0; i < 4; ++i)
        #pragma unroll
        for (int j = 0; j < 8; ++j)
            #pragma unroll
            for (int e = 0; e < 4; ++e) acc[i][j][e] = 0.f;

    auto load_chunk = [&](int c) {
        uint32_t sb = sbase + (uint32_t)(c & 1) * STAGEB;
        const __half* Ap = A + (size_t)m0 * lda + c * 128;
        const __half* Bp = B + (size_t)n0 * ldb + c * 128;
        #pragma unroll
        for (int q = 0; q < 8; ++q) {
            int t = tid + q * 256;
            int r = t >> 4, j = t & 15;
            uint32_t dst = sb + (uint32_t)(r * ROWB + j * 16);
            const void* src = Ap + (size_t)r * lda + j * 8;
            CP16(dst, src);
        }
        #pragma unroll
        for (int q = 0; q < 16; ++q) {
            int t = tid + q * 256;
            int r = (t >> 4) & 255, j = t & 15;
            uint32_t dst = sb + OFF_B + (uint32_t)(r * ROWB + j * 16);
            const void* src = Bp + (size_t)r * ldb + j * 8;
            CP16(dst, src);
        }
    };

    load_chunk(0);
    CP_COMMIT();

    for (int c = 0; c < k_chunks; ++c) {
        if (c + 1 < k_chunks) { load_chunk(c + 1); CP_COMMIT(); CP_WAIT1(); }
        else                  { CP_WAIT0(); }
        __syncthreads();

        uint32_t sb = sbase + (uint32_t)(c & 1) * STAGEB;
        uint32_t sA = sb + aoff;
        uint32_t sB = sb + OFF_B + boff;

        #pragma unroll
        for (int ks = 0; ks < 8; ++ks) {
            uint32_t kb = (uint32_t)(ks * 32);
            uint32_t bh[16], ah[16];
            // hoist ALL fragment loads for this ks before any MMA
            #pragma unroll
            for (int nb = 0; nb < 4; ++nb)
                LDMX4(bh[4*nb], bh[4*nb+1], bh[4*nb+2], bh[4*nb+3],
                      sB + kb + (uint32_t)(nb * 16 * ROWB));
            #pragma unroll
            for (int mi = 0; mi < 4; ++mi)
                LDMX4(ah[4*mi], ah[4*mi+1], ah[4*mi+2], ah[4*mi+3],
                      sA + kb + (uint32_t)(mi * 16 * ROWB));
            #pragma unroll
            for (int mi = 0; mi < 4; ++mi) {
                #pragma unroll
                for (int ni = 0; ni < 8; ++ni) {
                    MMA16816H(acc[mi][ni], &ah[4*mi], bh[2 * ni], bh[2 * ni + 1]);
                }
            }
        }
        __syncthreads();
    }

    #pragma unroll
    for (int mi = 0; mi < 4; ++mi) {
        int m = m0 + warp_m + mi * 16 + (lane >> 2);
        #pragma unroll
        for (int ni = 0; ni < 8; ++ni) {
            int n = n0 + warp_n + ni * 8 + (lane & 3) * 2;
            float b0 = bias[n], b1 = bias[n + 1];
            float v00 = acc[mi][ni][0] + b0, v01 = acc[mi][ni][1] + b1;
            float v10 = acc[mi][ni][2] + b0, v11 = acc[mi][ni][3] + b1;
            if (OUT_HALF) {
                __half* Ch = (__half*)Cv;
                *(uint32_t*)(Ch + (size_t)m * ldc + n) =
                    pack2h(__float2half_rn(v00), __float2half_rn(v01));
                *(uint32_t*)(Ch + (size_t)(m + 8) * ldc + n) =
                    pack2h(__float2half_rn(v10), __float2half_rn(v11));
            } else {
                float* Cf = (float*)Cv;
                *(float2*)(Cf + (size_t)m * ldc + n) = make_float2(v00, v01);
                *(float2*)(Cf + (size_t)(m + 8) * ldc + n) = make_float2(v10, v11);
            }
        }
    }
}

// ============================================================================
// fp16 HMMA attention: CTA per (window b, head h), 4 warps, 1-pass fp16.
// smem: Q[64x144B] K[64x144B] VT[64x144B] = 27648 B
// ============================================================================
#define AT_Q  0
#define AT_K  9216
#define AT_V  18432
#define ATTN_SMEM 27648

__global__ void __launch_bounds__(128) attn_kernel(const float* __restrict__ mask)
{
    extern __shared__ char sm[];
    uint32_t sb = smem_u32(sm);
    int b = blockIdx.x, h = blockIdx.y;
    int tid = threadIdx.x, wid = tid >> 5, lane = tid & 31;

    for (int i = tid; i < ATTN_SMEM / 16; i += 128)
        ((uint4*)sm)[i] = make_uint4(0u, 0u, 0u, 0u);
    __syncthreads();

    const __half* base = g_qkv + (size_t)b * 49 * 1536 + h * 64;

    for (int t = tid; t < 2 * 392; t += 128) {
        int ten = (t >= 392) ? 1 : 0;
        int rem = t - ten * 392;
        int row = rem >> 3, c8 = rem & 7;
        uint4 v = *(const uint4*)(base + ten * 512 + (size_t)row * 1536 + c8 * 8);
        *(uint4*)(sm + (ten ? AT_K : AT_Q) + row * 144 + c8 * 16) = v;
    }
    for (int t = tid; t < 392; t += 128) {
        int row = t >> 3, c8 = t & 7;
        uint4 v = *(const uint4*)(base + 1024 + (size_t)row * 1536 + c8 * 8);
        const __half* hv = (const __half*)&v;
        #pragma unroll
        for (int i = 0; i < 8; ++i) {
            int d = c8 * 8 + i;
            *(__half*)(sm + AT_V + d * 144 + row * 2) = hv[i];
        }
    }
    __syncthreads();

    uint32_t aoff = (uint32_t)((wid * 16 + (lane & 15)) * 144 + (lane >> 4) * 16);
    uint32_t boff = (uint32_t)(((((lane >> 4) << 3)) + (lane & 7)) * 144
                               + (((lane >> 3) & 1) << 4));

    float qa[8][4];
    #pragma unroll
    for (int ni = 0; ni < 8; ++ni)
        #pragma unroll
        for (int e = 0; e < 4; ++e) qa[ni][e] = 0.f;

    #pragma unroll
    for (int ks = 0; ks < 4; ++ks) {
        uint32_t kb = (uint32_t)(ks * 32);
        uint32_t bh[16], ah[4];
        #pragma unroll
        for (int nb = 0; nb < 4; ++nb)
            LDMX4(bh[4*nb], bh[4*nb+1], bh[4*nb+2], bh[4*nb+3],
                  sb + AT_K + boff + kb + (uint32_t)(nb * 16 * 144));
        LDMX4(ah[0], ah[1], ah[2], ah[3], sb + AT_Q + aoff + kb);
        #pragma unroll
        for (int ni = 0; ni < 8; ++ni)
            MMA16816H(qa[ni], ah, bh[2 * ni], bh[2 * ni + 1]);
    }

    int r0 = wid * 16 + (lane >> 2), r1 = r0 + 8;
    const float* mb = mask + (size_t)(b & 255) * 2401;
    #pragma unroll
    for (int ni = 0; ni < 8; ++ni) {
        int c = ni * 8 + (lane & 3) * 2;
        if (r0 < 49) {
            if (c < 49)     qa[ni][0] = qa[ni][0] * 0.125f + mb[r0 * 49 + c];
            else            qa[ni][0] = -1e30f;
            if (c + 1 < 49) qa[ni][1] = qa[ni][1] * 0.125f + mb[r0 * 49 + c + 1];
            else            qa[ni][1] = -1e30f;
        } else {
            qa[ni][0] = (c < 49) ? 0.f : -1e30f;
            qa[ni][1] = (c + 1 < 49) ? 0.f : -1e30f;
        }
        if (r1 < 49) {
            if (c < 49)     qa[ni][2] = qa[ni][2] * 0.125f + mb[r1 * 49 + c];
            else            qa[ni][2] = -1e30f;
            if (c + 1 < 49) qa[ni][3] = qa[ni][3] * 0.125f + mb[r1 * 49 + c + 1];
            else            qa[ni][3] = -1e30f;
        } else {
            qa[ni][2] = (c < 49) ? 0.f : -1e30f;
            qa[ni][3] = (c + 1 < 49) ? 0.f : -1e30f;
        }
    }
    float mx0 = -1e30f, mx1 = -1e30f;
    #pragma unroll
    for (int ni = 0; ni < 8; ++ni) {
        mx0 = fmaxf(mx0, fmaxf(qa[ni][0], qa[ni][1]));
        mx1 = fmaxf(mx1, fmaxf(qa[ni][2], qa[ni][3]));
    }
    mx0 = fmaxf(mx0, __shfl_xor_sync(0xFFFFFFFFu, mx0, 1));
    mx0 = fmaxf(mx0, __shfl_xor_sync(0xFFFFFFFFu, mx0, 2));
    mx1 = fmaxf(mx1, __shfl_xor_sync(0xFFFFFFFFu, mx1, 1));
    mx1 = fmaxf(mx1, __shfl_xor_sync(0xFFFFFFFFu, mx1, 2));
    float s0 = 0.f, s1 = 0.f;
    #pragma unroll
    for (int ni = 0; ni < 8; ++ni) {
        qa[ni][0] = __expf(qa[ni][0] - mx0); s0 += qa[ni][0];
        qa[ni][1] = __expf(qa[ni][1] - mx0); s0 += qa[ni][1];
        qa[ni][2] = __expf(qa[ni][2] - mx1); s1 += qa[ni][2];
        qa[ni][3] = __expf(qa[ni][3] - mx1); s1 += qa[ni][3];
    }
    s0 += __shfl_xor_sync(0xFFFFFFFFu, s0, 1);
    s0 += __shfl_xor_sync(0xFFFFFFFFu, s0, 2);
    s1 += __shfl_xor_sync(0xFFFFFFFFu, s1, 1);
    s1 += __shfl_xor_sync(0xFFFFFFFFu, s1, 2);
    float i0 = __fdividef(1.f, s0), i1 = __fdividef(1.f, s1);
    #pragma unroll
    for (int ni = 0; ni < 8; ++ni) {
        qa[ni][0] *= i0; qa[ni][1] *= i0;
        qa[ni][2] *= i1; qa[ni][3] *= i1;
    }

    float oa[8][4];
    #pragma unroll
    for (int ni = 0; ni < 8; ++ni)
        #pragma unroll
        for (int e = 0; e < 4; ++e) oa[ni][e] = 0.f;

    #pragma unroll
    for (int kk = 0; kk < 4; ++kk) {
        int n0i = 2 * kk, n1i = 2 * kk + 1;
        uint32_t ah[4];
        ah[0] = pack2h(__float2half_rn(qa[n0i][0]), __float2half_rn(qa[n0i][1]));
        ah[1] = pack2h(__float2half_rn(qa[n0i][2]), __float2half_rn(qa[n0i][3]));
        ah[2] = pack2h(__float2half_rn(qa[n1i][0]), __float2half_rn(qa[n1i][1]));
        ah[3] = pack2h(__float2half_rn(qa[n1i][2]), __float2half_rn(qa[n1i][3]));
        uint32_t kb = (uint32_t)(kk * 32);
        uint32_t bv[16];
        #pragma unroll
        for (int nb = 0; nb < 4; ++nb)
            LDMX4(bv[4*nb], bv[4*nb+1], bv[4*nb+2], bv[4*nb+3],
                  sb + AT_V + boff + kb + (uint32_t)(nb * 16 * 144));
        #pragma unroll
        for (int ni = 0; ni < 8; ++ni)
            MMA16816H(oa[ni], ah, bv[2 * ni], bv[2 * ni + 1]);
    }

    #pragma unroll
    for (int ni = 0; ni < 8; ++ni) {
        int c = ni * 8 + (lane & 3) * 2;
        if (r0 < 49) {
            size_t o = ((size_t)b * 49 + r0) * 512 + h * 64 + c;
            *(uint32_t*)&g_att[o] = pack2h(__float2half_rn(oa[ni][0]),
                                           __float2half_rn(oa[ni][1]));
        }
        if (r1 < 49) {
            size_t o = ((size_t)b * 49 + r1) * 512 + h * 64 + c;
            *(uint32_t*)&g_att[o] = pack2h(__float2half_rn(oa[ni][2]),
                                           __float2half_rn(oa[ni][3]));
        }
    }
}

// ============================================================================
// launch
// ============================================================================
extern "C" void kernel_launch(void* const* d_in, const int* in_sizes, int n_in,
                              void* d_out, int out_size)
{
    const float* x    = (const float*)d_in[0];
    const float* mask = (const float*)d_in[1];
    const float* Wq   = (const float*)d_in[2];
    const float* bq   = (const float*)d_in[3];
    const float* Wk   = (const float*)d_in[4];
    const float* bk   = (const float*)d_in[5];
    const float* Wv   = (const float*)d_in[6];
    const float* bv   = (const float*)d_in[7];
    const float* Wp   = (const float*)d_in[8];
    const float* bp   = (const float*)d_in[9];
    float* out = (float*)d_out;

    cudaFuncSetAttribute(gemm_kernel<true>,
                         cudaFuncAttributeMaxDynamicSharedMemorySize, GEMM_SMEM);
    cudaFuncSetAttribute(gemm_kernel<false>,
                         cudaFuncAttributeMaxDynamicSharedMemorySize, GEMM_SMEM);
    cudaFuncSetAttribute(attn_kernel,
                         cudaFuncAttributeMaxDynamicSharedMemorySize, ATTN_SMEM);

    __half *xh, *wqkv, *wp, *att, *qkv;
    float *bqkv;
    cudaGetSymbolAddress((void**)&xh,   g_x);
    cudaGetSymbolAddress((void**)&wqkv, g_wqkv);
    cudaGetSymbolAddress((void**)&wp,   g_wp);
    cudaGetSymbolAddress((void**)&att,  g_att);
    cudaGetSymbolAddress((void**)&qkv,  g_qkv);
    cudaGetSymbolAddress((void**)&bqkv, g_bqkv);

    prep_w_kernel<<<1024, 256>>>(Wq, Wk, Wv, bq, bk, bv, Wp);
    prep_x_kernel<<<8192, 256>>>(x);

    // GEMM1a: Q|K columns (n 0..1023), full K=1024 -> 4 n-tiles of 256, kc=8
    gemm_kernel<true><<<784 * 4, 256, GEMM_SMEM>>>(
        xh, K_QKV, wqkv, K_QKV, bqkv, qkv, N_QKV, 4, 8);

    // GEMM1b: V columns (n 1024..1535), real K=512 -> 2 n-tiles of 256, kc=4
    gemm_kernel<true><<<784 * 2, 256, GEMM_SMEM>>>(
        xh, K_QKV,
        wqkv + (size_t)1024 * K_QKV, K_QKV,
        bqkv + 1024, qkv + 1024, N_QKV, 2, 4);

    // attention (reads g_qkv fp16, writes g_att fp16)
    attn_kernel<<<dim3(2048, 8), 128, ATTN_SMEM>>>(mask);

    // GEMM2: out = att @ Wp + bp    (M=100352, K=512, N=1024) -> 4 n-tiles, kc=4
    gemm_kernel<false><<<784 * 4, 256, GEMM_SMEM>>>(
        att, K_PROJ, wp, K_PROJ, bp, out, N_PROJ, 4, 4);
}